// round 7
// baseline (speedup 1.0000x reference)
#include <cuda_runtime.h>
#include <math.h>

// ---------------- scratch (device globals; no allocations) ----------------
#define NB 16
__device__ float g_h1[NB*64*256*256];
__device__ float g_h2[NB*128*128*128];
__device__ float g_h3[NB*256*64*64];
__device__ float g_z [NB*512*32*32];
__device__ float g_zf[NB*1024*512];
__device__ float g_zq[NB*512*32*32];
__device__ float g_g1[NB*256*64*64];
__device__ float g_g2[NB*128*128*128];
__device__ float g_g3[NB*64*256*256];
__device__ float g_cn[8192];
__device__ int   g_idx[16384];

// ---------------- 3x3 conv, pad=1, 8-wide, TC output channels ----------------
// Thread: 8 horizontal outputs x TC output channels. Coalesced float4 loads,
// halo via shfl. Weights smem [ci][oc][ky][4] -> one LDS.128 per (oc,row).
// ACT: 0 none, 1 relu, 2 sigmoid
template<int STRIDE, int TC, int ACT>
__global__ void __launch_bounds__(128) conv8s_k(
    const float* __restrict__ in, const float* __restrict__ wgt,
    const float* __restrict__ bias, float* __restrict__ out,
    int Cin, int Cout, int Hin, int Win, int Hout, int Wout)
{
    constexpr int CICH = 32;
    constexpr int NW = (STRIDE == 1) ? 10 : 17;
    __shared__ float wsf[CICH * TC * 12];

    const int tid  = threadIdx.x;
    const int W8   = Wout >> 3;
    const int rows = 128 / W8;
    const int q    = tid % W8;
    const int oy   = blockIdx.y * rows + tid / W8;
    const int ox0  = q * 8;
    const int ocg  = blockIdx.x * TC;
    const int n    = blockIdx.z;

    float acc[TC][8];
#pragma unroll
    for (int o = 0; o < TC; o++)
#pragma unroll
        for (int j = 0; j < 8; j++) acc[o][j] = 0.f;

    bool rval[3]; int iyo[3];
#pragma unroll
    for (int ky = 0; ky < 3; ky++) {
        int iy = oy * STRIDE + ky - 1;
        rval[ky] = (iy >= 0 && iy < Hin);
        iyo[ky] = iy < 0 ? 0 : (iy >= Hin ? Hin - 1 : iy);
    }

    auto loadRow = [&](float (&w)[NW], int cabs, int ky) {
        const float* rp = in + ((size_t)(n * Cin + cabs) * Hin + iyo[ky]) * Win;
        if (STRIDE == 1) {
            float4 a = *(const float4*)(rp + ox0);
            float4 b = *(const float4*)(rp + ox0 + 4);
            float lft = __shfl_up_sync(0xffffffffu, b.w, 1);
            float rgt = __shfl_down_sync(0xffffffffu, a.x, 1);
            if (q == 0) lft = 0.f;
            if (q == W8 - 1) rgt = 0.f;
            w[0]=lft; w[1]=a.x; w[2]=a.y; w[3]=a.z; w[4]=a.w;
            w[5]=b.x; w[6]=b.y; w[7]=b.z; w[8]=b.w; w[9]=rgt;
        } else {
            const int ib = ox0 * 2;
            float4 a = *(const float4*)(rp + ib);
            float4 b = *(const float4*)(rp + ib + 4);
            float4 c = *(const float4*)(rp + ib + 8);
            float4 d = *(const float4*)(rp + ib + 12);
            float lft = __shfl_up_sync(0xffffffffu, d.w, 1);
            if (q == 0) lft = 0.f;
            w[0]=lft;
            w[1]=a.x; w[2]=a.y; w[3]=a.z; w[4]=a.w;
            w[5]=b.x; w[6]=b.y; w[7]=b.z; w[8]=b.w;
            w[9]=c.x; w[10]=c.y; w[11]=c.z; w[12]=c.w;
            w[13]=d.x; w[14]=d.y; w[15]=d.z; w[16]=d.w;
        }
        if (!rval[ky]) {
#pragma unroll
            for (int i = 0; i < NW; i++) w[i] = 0.f;
        }
    };

    auto computeRow = [&](float (&w)[NW], int ci, int ky) {
#pragma unroll
        for (int oc = 0; oc < TC; oc++) {
            const float4 wv = *(const float4*)(wsf + (ci * TC + oc) * 12 + ky * 4);
#pragma unroll
            for (int j = 0; j < 8; j++) {
                float a = acc[oc][j];
                a = fmaf(w[j * STRIDE + 0], wv.x, a);
                a = fmaf(w[j * STRIDE + 1], wv.y, a);
                a = fmaf(w[j * STRIDE + 2], wv.z, a);
                acc[oc][j] = a;
            }
        }
    };

    float bufA[NW], bufB[NW];
    for (int cc = 0; cc < Cin; cc += CICH) {
        const int chunk = min(CICH, Cin - cc);
        __syncthreads();
        for (int i = tid; i < chunk * TC * 9; i += 128) {
            int ci = i / (TC * 9);
            int r  = i - ci * (TC * 9);
            int oc = r / 9;
            int k  = r - oc * 9;
            wsf[(ci * TC + oc) * 12 + (k / 3) * 4 + (k % 3)] =
                wgt[(size_t)(ocg + oc) * Cin * 9 + (size_t)(cc + ci) * 9 + k];
        }
        __syncthreads();
        const int total = chunk * 3;
        loadRow(bufA, cc, 0);
        for (int m = 0; m < total; m++) {
            const int mn = m + 1;
            if (m & 1) {
                if (mn < total) loadRow(bufA, cc + mn / 3, mn % 3);
                computeRow(bufB, m / 3, m % 3);
            } else {
                if (mn < total) loadRow(bufB, cc + mn / 3, mn % 3);
                computeRow(bufA, m / 3, m % 3);
            }
        }
    }

#pragma unroll
    for (int oc = 0; oc < TC; oc++) {
        float bv = bias[ocg + oc];
        float* op = out + (((size_t)n * Cout + ocg + oc) * Hout + oy) * Wout + ox0;
        float v[8];
#pragma unroll
        for (int j = 0; j < 8; j++) {
            float a = acc[oc][j] + bv;
            if (ACT == 1) a = a > 0.f ? a : 0.f;
            if (ACT == 2) a = 1.f / (1.f + expf(-a));
            v[j] = a;
        }
        *(float4*)(op)     = make_float4(v[0], v[1], v[2], v[3]);
        *(float4*)(op + 4) = make_float4(v[4], v[5], v[6], v[7]);
    }
}

// ------- transposed conv k=3 s=2 p=1 op=1: 2x8 outputs, TC=4, coalesced -------
// Thread: output rows (2a, 2a+1), cols 8q..8q+7, for 4 ocs.
// Inputs: rows a, a+1, cols 4q..4q+4 (float4 + shfl). FMA order matches R1.
template<int ACT>
__global__ void __launch_bounds__(128) deconv48_k(
    const float* __restrict__ in, const float* __restrict__ wgt,  // [Cin][Cout][3][3]
    const float* __restrict__ bias, float* __restrict__ out,
    int Cin, int Cout, int Hin, int Win)
{
    constexpr int CICH = 32;
    constexpr int TC = 4;
    __shared__ float wsf[CICH * TC * 12];  // 6KB

    const int Hout = Hin * 2, Wout = Win * 2;
    const int tid  = threadIdx.x;
    const int W8   = Wout >> 3;            // = Win/4
    const int rpb  = 128 / W8;             // input rows per block
    const int q    = tid % W8;
    const int a    = blockIdx.y * rpb + tid / W8;   // input row
    const int ocg  = blockIdx.x * TC;
    const int n    = blockIdx.z;

    const bool v_a1 = (a + 1) < Hin;
    const int  a1c  = v_a1 ? (a + 1) : a;
    const bool last = (q == W8 - 1);

    float acc[TC][16];   // [oc][dr*8 + j]
#pragma unroll
    for (int o = 0; o < TC; o++)
#pragma unroll
        for (int j = 0; j < 16; j++) acc[o][j] = 0.f;

    // w[0..4] = row a cols 4q..4q+4 ; w[5..9] = row a+1 (or 0)
    auto loadRaw = [&](float (&w)[10], int cabs) {
        const float* ip = in + (size_t)(n * Cin + cabs) * Hin * Win;
        const float* r0 = ip + (size_t)a * Win + 4 * q;
        const float* r1 = ip + (size_t)a1c * Win + 4 * q;
        float4 v0 = *(const float4*)r0;
        float4 v1 = *(const float4*)r1;
        float e0 = __shfl_down_sync(0xffffffffu, v0.x, 1);
        float e1 = __shfl_down_sync(0xffffffffu, v1.x, 1);
        if (last) { e0 = 0.f; e1 = 0.f; }
        w[0]=v0.x; w[1]=v0.y; w[2]=v0.z; w[3]=v0.w; w[4]=e0;
        if (v_a1) { w[5]=v1.x; w[6]=v1.y; w[7]=v1.z; w[8]=v1.w; w[9]=e1; }
        else      { w[5]=0.f; w[6]=0.f; w[7]=0.f; w[8]=0.f; w[9]=0.f; }
    };

    auto computeCi = [&](float (&w)[10], int ci) {
#pragma unroll
        for (int oc = 0; oc < TC; oc++) {
            const float* wp = wsf + (ci * TC + oc) * 12;
            const float4 A = *(const float4*)(wp);       // w00 w01 w02 w10
            const float4 B = *(const float4*)(wp + 4);   // w11 w12 w20 w21
            const float w22 = wp[8];
            float w00=A.x, w01=A.y, w02=A.z, w10=A.w;
            float w11=B.x, w12=B.y, w20=B.z, w21=B.w;
#pragma unroll
            for (int m = 0; m < 4; m++) {
                // row 2a, even col: w11 on r0[m]
                acc[oc][2*m]     = fmaf(w[m], w11, acc[oc][2*m]);
                // row 2a, odd col: (r0[m+1]*w10) then (r0[m]*w12)  [R1 order]
                acc[oc][2*m+1]   = fmaf(w[m], w12, fmaf(w[m+1], w10, acc[oc][2*m+1]));
                // row 2a+1, even col: (r1[m]*w01) then (r0[m]*w21)
                acc[oc][8+2*m]   = fmaf(w[m], w21, fmaf(w[5+m], w01, acc[oc][8+2*m]));
                // row 2a+1, odd col: r1[m+1]*w00, r1[m]*w02, r0[m+1]*w20, r0[m]*w22
                acc[oc][8+2*m+1] = fmaf(w[m], w22, fmaf(w[m+1], w20,
                                    fmaf(w[5+m], w02, fmaf(w[5+m+1], w00, acc[oc][8+2*m+1]))));
            }
        }
    };

    float rawA[10], rawB[10];
    for (int cc = 0; cc < Cin; cc += CICH) {
        const int chunk = min(CICH, Cin - cc);
        __syncthreads();
        for (int i = tid; i < chunk * TC * 9; i += 128) {
            int ci = i / (TC * 9);
            int r  = i - ci * (TC * 9);
            int oc = r / 9;
            int k  = r - oc * 9;
            wsf[(ci * TC + oc) * 12 + k] =
                wgt[(size_t)(cc + ci) * Cout * 9 + (size_t)(ocg + oc) * 9 + k];
        }
        __syncthreads();
        loadRaw(rawA, cc);
        for (int ci = 0; ci < chunk; ci += 2) {
            if (ci + 1 < chunk) loadRaw(rawB, cc + ci + 1);
            computeCi(rawA, ci);
            if (ci + 2 < chunk) loadRaw(rawA, cc + ci + 2);
            if (ci + 1 < chunk) computeCi(rawB, ci + 1);
        }
    }

#pragma unroll
    for (int oc = 0; oc < TC; oc++) {
        float bv = bias[ocg + oc];
        float* o0 = out + (((size_t)n * Cout + ocg + oc) * Hout + 2 * a) * Wout + 8 * q;
        float* o1 = o0 + Wout;
        float v0[8], v1[8];
#pragma unroll
        for (int j = 0; j < 8; j++) {
            float x0 = acc[oc][j] + bv;
            float x1 = acc[oc][8 + j] + bv;
            if (ACT == 1) { x0 = x0 > 0.f ? x0 : 0.f; x1 = x1 > 0.f ? x1 : 0.f; }
            v0[j] = x0; v1[j] = x1;
        }
        *(float4*)(o0)     = make_float4(v0[0], v0[1], v0[2], v0[3]);
        *(float4*)(o0 + 4) = make_float4(v0[4], v0[5], v0[6], v0[7]);
        *(float4*)(o1)     = make_float4(v1[0], v1[1], v1[2], v1[3]);
        *(float4*)(o1 + 4) = make_float4(v1[4], v1[5], v1[6], v1[7]);
    }
}

// ---------------- z [B,512,32,32] -> zf [16384, 512] ----------------
__global__ void __launch_bounds__(256) zt_k(const float* __restrict__ z,
                                            float* __restrict__ zf)
{
    __shared__ float t[128 * 33];
    const int blk = blockIdx.x;
    const int bb  = blk >> 5;
    const int y   = blk & 31;
    const int tid = threadIdx.x;
    for (int cc = 0; cc < 512; cc += 128) {
        __syncthreads();
        for (int i = tid; i < 128 * 32; i += 256) {
            int c = i >> 5, x = i & 31;
            t[c * 33 + x] = z[(((size_t)bb * 512 + cc + c) * 32 + y) * 32 + x];
        }
        __syncthreads();
        for (int i = tid; i < 32 * 128; i += 256) {
            int x = i >> 7, c = i & 127;
            zf[((size_t)bb * 1024 + y * 32 + x) * 512 + cc + c] = t[c * 33 + x];
        }
    }
}

// ---------------- codebook row norms ----------------
__global__ void __launch_bounds__(256) cnorm_k(const float* __restrict__ cb,
                                               float* __restrict__ cn)
{
    const int warp = threadIdx.x >> 5, lane = threadIdx.x & 31;
    const int code = blockIdx.x * 8 + warp;
    const float* p = cb + (size_t)code * 512;
    float s = 0.f;
    for (int d = lane; d < 512; d += 32) { float v = p[d]; s = fmaf(v, v, s); }
#pragma unroll
    for (int o = 16; o > 0; o >>= 1) s += __shfl_xor_sync(0xffffffffu, s, o);
    if (lane == 0) cn[code] = s;
}

// ---------------- quantizer: 32 rows/block, thread = 8 rows x 8 codes ---------
#define ZPQ 520
#define CPQ 20
__global__ void __launch_bounds__(512) quant8_k(const float* __restrict__ zf,
                                                const float* __restrict__ cb,
                                                const float* __restrict__ cn,
                                                int* __restrict__ idx)
{
    extern __shared__ float sm[];
    float* zs  = sm;                 // 32*520
    float* cbt = sm + 32 * ZPQ;      // 2 * 1024*20
    const int tid = threadIdx.x;
    const int t   = tid & 127;
    const int rg  = tid >> 7;
    const int r0  = blockIdx.x * 32;

    for (int i = tid; i < 32 * 128; i += 512) {
        int r = i >> 7, dq = i & 127;
        float4 v = *(const float4*)(zf + (size_t)(r0 + r) * 512 + dq * 4);
        *(float4*)(zs + r * ZPQ + dq * 4) = v;
    }

    float best[8]; int bi[8];
#pragma unroll
    for (int r = 0; r < 8; r++) { best[r] = 3.4e38f; bi[r] = 0; }

    auto stage = [&](int cbase, int dch, int buf) {
        float* dst = cbt + buf * (1024 * CPQ);
        for (int i = tid; i < 4096; i += 512) {
            int c = i >> 2, dq = i & 3;
            float4 v = *(const float4*)(cb + (size_t)(cbase + c) * 512 + dch * 16 + dq * 4);
            *(float4*)(dst + c * CPQ + dq * 4) = v;
        }
    };

    for (int ct = 0; ct < 8; ct++) {
        const int cbase = ct * 1024;
        float acc[8][8];
#pragma unroll
        for (int rr = 0; rr < 8; rr++)
#pragma unroll
            for (int k = 0; k < 8; k++) acc[rr][k] = 0.f;

        __syncthreads();
        stage(cbase, 0, 0);
        for (int dch = 0; dch < 32; dch++) {
            __syncthreads();
            if (dch + 1 < 32) stage(cbase, dch + 1, (dch + 1) & 1);
            const float* cbuf = cbt + (dch & 1) * (1024 * CPQ);
#pragma unroll
            for (int dq = 0; dq < 4; dq++) {
                float4 zv[8];
#pragma unroll
                for (int rr = 0; rr < 8; rr++)
                    zv[rr] = *(const float4*)(zs + (rg * 8 + rr) * ZPQ + dch * 16 + dq * 4);
#pragma unroll
                for (int k = 0; k < 8; k++) {
                    float4 cv = *(const float4*)(cbuf + (k * 128 + t) * CPQ + dq * 4);
#pragma unroll
                    for (int rr = 0; rr < 8; rr++) {
                        float a = acc[rr][k];
                        a = fmaf(zv[rr].x, cv.x, a);
                        a = fmaf(zv[rr].y, cv.y, a);
                        a = fmaf(zv[rr].z, cv.z, a);
                        a = fmaf(zv[rr].w, cv.w, a);
                        acc[rr][k] = a;
                    }
                }
            }
        }
#pragma unroll
        for (int k = 0; k < 8; k++) {
            int cand = cbase + k * 128 + t;
            float nv = cn[cand];
#pragma unroll
            for (int rr = 0; rr < 8; rr++) {
                float s = nv - 2.f * acc[rr][k];
                if (s < best[rr]) { best[rr] = s; bi[rr] = cand; }
            }
        }
    }

    float* sv = sm;
    int*   si = (int*)(sm + 512);
    for (int rr = 0; rr < 8; rr++) {
        __syncthreads();
        sv[tid] = best[rr]; si[tid] = bi[rr];
        __syncthreads();
        for (int s = 64; s > 0; s >>= 1) {
            if (t < s) {
                float ov = sv[tid + s]; int oi = si[tid + s];
                if (ov < sv[tid] || (ov == sv[tid] && oi < si[tid])) { sv[tid] = ov; si[tid] = oi; }
            }
            __syncthreads();
        }
        if (t == 0) idx[r0 + rg * 8 + rr] = si[tid];
    }
}

// ---------------- zq gather ----------------
__global__ void __launch_bounds__(256) zqg_k(const float* __restrict__ cb,
                                             const int* __restrict__ idx,
                                             float* __restrict__ zq)
{
    size_t i = (size_t)blockIdx.x * 256 + threadIdx.x;
    if (i >= (size_t)NB * 512 * 32 * 32) return;
    int x = (int)(i & 31);
    int y = (int)((i >> 5) & 31);
    int c = (int)((i >> 10) & 511);
    int bb = (int)(i >> 19);
    int n = bb * 1024 + y * 32 + x;
    zq[i] = cb[(size_t)idx[n] * 512 + c];
}

// ---------------- indices -> tail of output ----------------
__global__ void __launch_bounds__(256) idxout_k(const int* __restrict__ idx,
                                                float* __restrict__ out,
                                                long out_off, long out_size)
{
    int i = blockIdx.x * 256 + threadIdx.x;
    if (i < 16384 && out_off + i < out_size) out[out_off + i] = (float)idx[i];
}

// ---------------- host launcher ----------------
extern "C" void kernel_launch(void* const* d_in, const int* in_sizes, int n_in,
                              void* d_out, int out_size)
{
    const float* x  = (const float*)d_in[0];
    const float* w1 = (const float*)d_in[1];  const float* b1 = (const float*)d_in[2];
    const float* w2 = (const float*)d_in[3];  const float* b2 = (const float*)d_in[4];
    const float* w3 = (const float*)d_in[5];  const float* b3 = (const float*)d_in[6];
    const float* w4 = (const float*)d_in[7];  const float* b4 = (const float*)d_in[8];
    const float* cb = (const float*)d_in[9];
    const float* d1w = (const float*)d_in[10]; const float* d1b = (const float*)d_in[11];
    const float* d2w = (const float*)d_in[12]; const float* d2b = (const float*)d_in[13];
    const float* d3w = (const float*)d_in[14]; const float* d3b = (const float*)d_in[15];
    const float* wo = (const float*)d_in[16]; const float* bo = (const float*)d_in[17];
    float* out = (float*)d_out;

    float *h1, *h2, *h3, *z, *zf, *zq, *g1, *g2, *g3, *cn;
    int* idx;
    cudaGetSymbolAddress((void**)&h1, g_h1);
    cudaGetSymbolAddress((void**)&h2, g_h2);
    cudaGetSymbolAddress((void**)&h3, g_h3);
    cudaGetSymbolAddress((void**)&z,  g_z);
    cudaGetSymbolAddress((void**)&zf, g_zf);
    cudaGetSymbolAddress((void**)&zq, g_zq);
    cudaGetSymbolAddress((void**)&g1, g_g1);
    cudaGetSymbolAddress((void**)&g2, g_g2);
    cudaGetSymbolAddress((void**)&g3, g_g3);
    cudaGetSymbolAddress((void**)&cn, g_cn);
    cudaGetSymbolAddress((void**)&idx, g_idx);

    // codebook norms first (independent)
    cnorm_k<<<1024, 256>>>(cb, cn);

    // Encoder
    conv8s_k<1, 8, 1><<<dim3( 8, 64, NB), 128>>>(x,  w1, b1, h1,   3,  64, 256, 256, 256, 256);
    conv8s_k<2, 8, 1><<<dim3(16, 16, NB), 128>>>(h1, w2, b2, h2,  64, 128, 256, 256, 128, 128);
    conv8s_k<2, 8, 1><<<dim3(32,  4, NB), 128>>>(h2, w3, b3, h3, 128, 256, 128, 128,  64,  64);
    conv8s_k<2, 8, 0><<<dim3(64,  1, NB), 128>>>(h3, w4, b4, z,  256, 512,  64,  64,  32,  32);

    // Quantize
    zt_k<<<512, 256>>>(z, zf);
    const int qsmem = (32 * ZPQ + 2 * 1024 * CPQ) * 4;  // 230400 B
    cudaFuncSetAttribute(quant8_k, cudaFuncAttributeMaxDynamicSharedMemorySize, qsmem);
    quant8_k<<<512, 512, qsmem>>>(zf, cb, cn, idx);
    zqg_k<<<(NB * 512 * 32 * 32 + 255) / 256, 256>>>(cb, idx, zq);

    // Decoder (2x8-wide TC=4 deconv)
    deconv48_k<1><<<dim3(64,  2, NB), 128>>>(zq, d1w, d1b, g1, 512, 256,  32,  32);
    deconv48_k<1><<<dim3(32,  8, NB), 128>>>(g1, d2w, d2b, g2, 256, 128,  64,  64);
    deconv48_k<1><<<dim3(16, 32, NB), 128>>>(g2, d3w, d3b, g3, 128,  64, 128, 128);
    // Final sigmoid conv: 8-wide, TC=3
    conv8s_k<1, 3, 2><<<dim3(1, 64, NB), 128>>>(g3, wo, bo, out, 64, 3, 256, 256, 256, 256);

    // Indices appended after reconstruction
    idxout_k<<<64, 256>>>(idx, out, (long)NB * 3 * 256 * 256, (long)out_size);
}